// round 5
// baseline (speedup 1.0000x reference)
#include <cuda_runtime.h>
#include <math.h>

#define IN_C   64
#define OUT_C  64
#define NUM_RELS 32
#define N_NODES 20000
#define N_EDGES 50000
#define CHUNKS 7
#define EDGE_BLOCKS ((N_EDGES + 255) / 256)     // 196

// ---------------- device scratch ----------------
// contiguous counter block: [0,N) src deg | [N,2N) dst deg | [2N,2N+32) cursors
__device__ __align__(16) int g_cnt[2 * N_NODES + NUM_RELS];
__device__ float g_wscale[2 * NUM_RELS];        // 1/(||W||+0.01) per (dir,type)
__device__ int   g_bsrc[NUM_RELS * N_EDGES];    // per-type buckets (cap = N_EDGES)
__device__ int   g_bdst[NUM_RELS * N_EDGES];

// ---- packed f32x2 helpers ----
__device__ __forceinline__ void fma2(unsigned long long& d,
                                     unsigned long long a, unsigned long long b) {
    asm("fma.rn.f32x2 %0, %1, %2, %0;" : "+l"(d) : "l"(a), "l"(b));
}
__device__ __forceinline__ unsigned long long pack2(float v) {
    unsigned long long r;
    asm("mov.b64 %0, {%1, %1};" : "=l"(r) : "f"(v));
    return r;
}
__device__ __forceinline__ void mul2(unsigned long long& d,
                                     unsigned long long a, unsigned long long b) {
    asm("mul.rn.f32x2 %0, %1, %2;" : "=l"(d) : "l"(a), "l"(b));
}
__device__ __forceinline__ void unpack2(unsigned long long v, float& lo, float& hi) {
    asm("mov.b64 {%0, %1}, %2;" : "=f"(lo), "=f"(hi) : "l"(v));
}
__device__ __forceinline__ unsigned long long d_as_ull(double d) {
    return __double_as_longlong(d);
}

// ---------------- k_main: degrees + bucket scatter + weight sumsq ------------
// blocks [0, EDGE_BLOCKS): one edge per thread
// blocks [EDGE_BLOCKS, EDGE_BLOCKS+64): one weight matrix sumsq per block
__global__ void __launch_bounds__(256) k_main(const int* __restrict__ ei,
                                              const int* __restrict__ et,
                                              const float* __restrict__ wf,
                                              const float* __restrict__ wb) {
    int b = blockIdx.x;
    if (b < EDGE_BLOCKS) {
        __shared__ int lh[NUM_RELS];
        __shared__ int lbase[NUM_RELS];
        if (threadIdx.x < NUM_RELS) lh[threadIdx.x] = 0;
        __syncthreads();
        int e = b * 256 + threadIdx.x;
        int s = 0, d = 0, t = -1, myrank = 0;
        if (e < N_EDGES) {
            s = ei[e];
            d = ei[N_EDGES + e];
            t = et[e];
            atomicAdd(&g_cnt[s], 1);
            atomicAdd(&g_cnt[N_NODES + d], 1);
            myrank = atomicAdd(&lh[t], 1);
        }
        __syncthreads();
        if (threadIdx.x < NUM_RELS) {
            int c = lh[threadIdx.x];
            lbase[threadIdx.x] = c ? atomicAdd(&g_cnt[2 * N_NODES + threadIdx.x], c) : 0;
        }
        __syncthreads();
        if (e < N_EDGES) {
            int p = t * N_EDGES + lbase[t] + myrank;
            g_bsrc[p] = s;
            g_bdst[p] = d;
        }
    } else {
        // weight sumsq: m in [0,64); m<32 -> wf row m, else wb row m-32
        int m = b - EDGE_BLOCKS;
        const float4* src = (const float4*)((m < NUM_RELS)
                            ? (wf + (size_t)m * 4096)
                            : (wb + (size_t)(m - NUM_RELS) * 4096));
        __shared__ float red[8];
        float s = 0.f;
        #pragma unroll
        for (int j = 0; j < 4; j++) {
            float4 v = src[threadIdx.x + j * 256];
            s += v.x * v.x + v.y * v.y + v.z * v.z + v.w * v.w;
        }
        #pragma unroll
        for (int dd = 16; dd > 0; dd >>= 1) s += __shfl_xor_sync(0xffffffffu, s, dd);
        if ((threadIdx.x & 31) == 0) red[threadIdx.x >> 5] = s;
        __syncthreads();
        if (threadIdx.x == 0) {
            float tot = 0.f;
            #pragma unroll
            for (int w = 0; w < 8; w++) tot += red[w];
            g_wscale[m] = 1.0f / (sqrtf(tot) + 0.01f);
        }
    }
}

// ---------------- k_linear: out = x @ lin_w^T + lin_b (f32x2) ----------------
__global__ void __launch_bounds__(256) k_linear(const float* __restrict__ x,
                                                const float* __restrict__ lw,
                                                const float* __restrict__ lb,
                                                float* __restrict__ out) {
    __shared__ __align__(16) float Ls[64 * 64];   // Ls[i*64+o] = lw[o*64+i]
    __shared__ float Bs[64];
    for (int j = threadIdx.x; j < 4096; j += 256) {
        int o = j >> 6, i = j & 63;
        Ls[i * 64 + o] = lw[j];
    }
    if (threadIdx.x < 64) Bs[threadIdx.x] = lb[threadIdx.x];
    __syncthreads();

    int n = blockIdx.x * 256 + threadIdx.x;
    if (n >= N_NODES) return;

    unsigned long long acc[32];
    #pragma unroll
    for (int k = 0; k < 32; k++) acc[k] = 0ull;

    const float4* xr = (const float4*)(x + (size_t)n * 64);
    #pragma unroll 1
    for (int i4 = 0; i4 < 16; i4++) {
        float4 v = xr[i4];
        float vs[4] = {v.x, v.y, v.z, v.w};
        #pragma unroll
        for (int j = 0; j < 4; j++) {
            unsigned long long vv = pack2(vs[j]);
            const double2* wrow = (const double2*)(Ls + ((i4 * 4 + j) << 6));
            #pragma unroll
            for (int o4 = 0; o4 < 16; o4++) {
                double2 w = wrow[o4];
                fma2(acc[2 * o4], vv, d_as_ull(w.x));
                fma2(acc[2 * o4 + 1], vv, d_as_ull(w.y));
            }
        }
    }
    float4* outr = (float4*)(out + (size_t)n * 64);
    const float4* B4 = (const float4*)Bs;
    #pragma unroll
    for (int o = 0; o < 16; o++) {
        float a0, a1, a2, a3;
        unpack2(acc[2 * o], a0, a1);
        unpack2(acc[2 * o + 1], a2, a3);
        float4 b = B4[o];
        outr[o] = make_float4(a0 + b.x, a1 + b.y, a2 + b.z, a3 + b.w);
    }
}

// ---------------- k_edge: per-(dir,type,chunk) edge matmul + scatter ---------
__global__ void __launch_bounds__(256) k_edge(const float* __restrict__ x,
                                              const float* __restrict__ wf,
                                              const float* __restrict__ wb,
                                              float* __restrict__ out) {
    __shared__ __align__(16) float Ws[4096];
    int b = blockIdx.x;
    int dir = b & 1;
    int t = (b >> 1) & 31;
    int chunk = b >> 6;          // 0..CHUNKS-1

    const float4* Wg = (const float4*)(((dir == 0) ? wf : wb) + (size_t)t * 4096);
    float4* Ws4w = (float4*)Ws;
    for (int j = threadIdx.x; j < 1024; j += 256) Ws4w[j] = Wg[j];
    __syncthreads();

    int count = g_cnt[2 * N_NODES + t];
    float wsc = g_wscale[dir * NUM_RELS + t];
    const int* bsrc = g_bsrc + t * N_EDGES;
    const int* bdst = g_bdst + t * N_EDGES;

    for (int idx = chunk * 256 + threadIdx.x; idx < count; idx += 256 * CHUNKS) {
        int row, onode;
        float scale;
        if (dir == 0) {
            row = bsrc[idx]; onode = bdst[idx];
            scale = wsc * __fdividef(1.0f, (float)(g_cnt[row] + 1));
        } else {
            row = bdst[idx]; onode = bsrc[idx];
            scale = wsc * __fdividef(1.0f, (float)(g_cnt[N_NODES + row] + 1));
        }

        unsigned long long acc[32];
        #pragma unroll
        for (int k = 0; k < 32; k++) acc[k] = 0ull;

        const float4* xr = (const float4*)(x + (size_t)row * 64);
        #pragma unroll 1
        for (int i4 = 0; i4 < 16; i4++) {
            float4 v = xr[i4];
            float vs[4] = {v.x, v.y, v.z, v.w};
            #pragma unroll
            for (int j = 0; j < 4; j++) {
                unsigned long long vv = pack2(vs[j]);
                const double2* wrow = (const double2*)(Ws + ((i4 * 4 + j) << 6));
                #pragma unroll
                for (int o4 = 0; o4 < 16; o4++) {
                    double2 w = wrow[o4];      // LDS.128 broadcast -> two f32x2
                    fma2(acc[2 * o4], vv, d_as_ull(w.x));
                    fma2(acc[2 * o4 + 1], vv, d_as_ull(w.y));
                }
            }
        }

        unsigned long long ss = pack2(scale);
        float* op = out + (size_t)onode * 64;
        #pragma unroll
        for (int o = 0; o < 16; o++) {
            unsigned long long p0, p1;
            mul2(p0, acc[2 * o], ss);
            mul2(p1, acc[2 * o + 1], ss);
            float a0, a1, a2, a3;
            unpack2(p0, a0, a1);
            unpack2(p1, a2, a3);
            asm volatile("red.global.add.v4.f32 [%0], {%1, %2, %3, %4};"
                         :: "l"(op + o * 4), "f"(a0), "f"(a1), "f"(a2), "f"(a3)
                         : "memory");
        }
    }
}

// ---------------- launch: memset -> main -> edge, linear forked --------------
extern "C" void kernel_launch(void* const* d_in, const int* in_sizes, int n_in,
                              void* d_out, int out_size) {
    const float* x   = (const float*)d_in[0];
    const int*   ei  = (const int*)d_in[1];     // [2, E] int32
    const int*   et  = (const int*)d_in[2];     // [E]    int32
    const float* wf  = (const float*)d_in[3];
    const float* wb  = (const float*)d_in[4];
    const float* lw  = (const float*)d_in[5];
    const float* lb  = (const float*)d_in[6];
    float*       out = (float*)d_out;

    (void)in_sizes; (void)n_in; (void)out_size;

    void* cntAddr = nullptr;
    cudaGetSymbolAddress(&cntAddr, g_cnt);

    cudaStream_t sB;
    cudaEvent_t evRoot, evB;
    cudaStreamCreateWithFlags(&sB, cudaStreamNonBlocking);
    cudaEventCreateWithFlags(&evRoot, cudaEventDisableTiming);
    cudaEventCreateWithFlags(&evB, cudaEventDisableTiming);

    // fork side stream off the (captured) legacy stream
    cudaEventRecord(evRoot, 0);
    cudaStreamWaitEvent(sB, evRoot, 0);

    // chain A: zero counters -> main (degrees + buckets + wscale)
    cudaMemsetAsync(cntAddr, 0, sizeof(int) * (2 * N_NODES + NUM_RELS), 0);
    k_main<<<EDGE_BLOCKS + 2 * NUM_RELS, 256>>>(ei, et, wf, wb);

    // chain B: dense linear writes out
    k_linear<<<(N_NODES + 255) / 256, 256, 0, sB>>>(x, lw, lb, out);
    cudaEventRecord(evB, sB);

    // join, then edge kernel
    cudaStreamWaitEvent(0, evB, 0);
    k_edge<<<2 * NUM_RELS * CHUNKS, 256>>>(x, wf, wb, out);

    cudaEventDestroy(evRoot);
    cudaEventDestroy(evB);
    cudaStreamDestroy(sB);
}